// round 12
// baseline (speedup 1.0000x reference)
#include <cuda_runtime.h>
#include <cstdint>

#define NN 1000000
#define NE 16000000

// ---- scratch (device globals; no allocations allowed) ----
// g_deg is zero at module load; every call re-zeroes it in k_out's tail,
// so each kernel_launch call sees deg==0 at entry (state invariant).
__device__ int    g_deg[NN];
__device__ float  g_u[NN];
__device__ float  g_acc1[NN];    // initialized to u[i] (self-loop term)
__device__ float2 g_t[NN];
__device__ float2 g_acc2[NN];    // initialized to t[i] (self-loop term)

// folded MLP coefficients (valid iff b1 == 0): g(s) = s>0 ? s*Ap : s*Am
__device__ float  g_Ap[2];
__device__ float  g_Am[2];
__device__ int    g_fullpath;   // nonzero if any b1[j] != 0 -> exact full MLP

// ---- no-return global reductions ----
__device__ __forceinline__ void red_add_u32(int* addr) {
    asm volatile("red.global.add.u32 [%0], 1;" :: "l"(addr) : "memory");
}
__device__ __forceinline__ void red_add_f32(float* addr, float v) {
    asm volatile("red.global.add.f32 [%0], %1;" :: "l"(addr), "f"(v) : "memory");
}
__device__ __forceinline__ void red_add_v2(float2* addr, float2 v) {
    asm volatile("red.global.add.v2.f32 [%0], {%1, %2};"
                 :: "l"(addr), "f"(v.x), "f"(v.y) : "memory");
}

// ---------------------------------------------------------------------------
// degree count over target (col) indices; 4 edges per thread (flat mapping)
__global__ __launch_bounds__(256) void k_deg(const int* __restrict__ col, int E) {
    int i = (blockIdx.x * blockDim.x + threadIdx.x) * 4;
    if (i + 3 < E) {
        int4 c = __ldcs(reinterpret_cast<const int4*>(col + i));
        red_add_u32(&g_deg[c.x]);
        red_add_u32(&g_deg[c.y]);
        red_add_u32(&g_deg[c.z]);
        red_add_u32(&g_deg[c.w]);
    }
}

// u = rsqrt(deg+1) * x; acc1 = u (self-loop term). 4 nodes/thread.
// Extra block (blockIdx.x == gridDim.x-1) folds MLP weights into A+/A-.
__global__ __launch_bounds__(256) void k_prep(const float4* __restrict__ x4,
                                              const float* __restrict__ W1,
                                              const float* __restrict__ b1,
                                              const float* __restrict__ W2) {
    if (blockIdx.x == gridDim.x - 1) {
        if (threadIdx.x < 32) {
            int j = threadIdx.x;
            float w   = (j < 16) ? W1[j] : 0.0f;
            float bb  = (j < 16) ? b1[j] : 0.0f;
            float w20 = (j < 16) ? W2[2 * j]     : 0.0f;
            float w21 = (j < 16) ? W2[2 * j + 1] : 0.0f;
            float ap0 = (w > 0.0f) ? w * w20 : 0.0f;
            float ap1 = (w > 0.0f) ? w * w21 : 0.0f;
            float am0 = (w < 0.0f) ? w * w20 : 0.0f;
            float am1 = (w < 0.0f) ? w * w21 : 0.0f;
            int   nz  = (bb != 0.0f) ? 1 : 0;
#pragma unroll
            for (int off = 16; off > 0; off >>= 1) {
                ap0 += __shfl_down_sync(0xffffffffu, ap0, off);
                ap1 += __shfl_down_sync(0xffffffffu, ap1, off);
                am0 += __shfl_down_sync(0xffffffffu, am0, off);
                am1 += __shfl_down_sync(0xffffffffu, am1, off);
                nz  += __shfl_down_sync(0xffffffffu, nz,  off);
            }
            if (j == 0) {
                g_Ap[0] = ap0; g_Ap[1] = ap1;
                g_Am[0] = am0; g_Am[1] = am1;
                g_fullpath = nz;
            }
        }
        return;
    }
    int i = blockIdx.x * blockDim.x + threadIdx.x;
    if (i >= NN / 4) return;
    int4   dg = reinterpret_cast<const int4*>(g_deg)[i];
    float4 xv = __ldg(&x4[i]);
    float4 u;
    u.x = rsqrtf((float)(dg.x + 1)) * xv.x;
    u.y = rsqrtf((float)(dg.y + 1)) * xv.y;
    u.z = rsqrtf((float)(dg.z + 1)) * xv.z;
    u.w = rsqrtf((float)(dg.w + 1)) * xv.w;
    reinterpret_cast<float4*>(g_u)[i]    = u;
    reinterpret_cast<float4*>(g_acc1)[i] = u;   // self-loop folded into init
}

// scatter layer-1 messages: acc1[col] += u[row]; 4 edges per thread
__global__ __launch_bounds__(256) void k_scat1(const int* __restrict__ row,
                                               const int* __restrict__ col, int E) {
    int i = (blockIdx.x * blockDim.x + threadIdx.x) * 4;
    if (i + 3 < E) {
        int4 r = __ldcs(reinterpret_cast<const int4*>(row + i));
        int4 c = __ldcs(reinterpret_cast<const int4*>(col + i));
        float u0 = __ldg(&g_u[r.x]);
        float u1 = __ldg(&g_u[r.y]);
        float u2 = __ldg(&g_u[r.z]);
        float u3 = __ldg(&g_u[r.w]);
        red_add_f32(&g_acc1[c.x], u0);
        red_add_f32(&g_acc1[c.y], u1);
        red_add_f32(&g_acc1[c.z], u2);
        red_add_f32(&g_acc1[c.w], u3);
    }
}

// full exact MLP (fallback path, used only if b1 != 0)
__device__ __noinline__ void mlp_full(float s, const float4* W1,
                                      const float4* b1, const float4* W2,
                                      float& g0, float& g1) {
    g0 = 0.0f; g1 = 0.0f;
#pragma unroll
    for (int q = 0; q < 4; q++) {
        float4 w1 = __ldg(&W1[q]);
        float4 bb = __ldg(&b1[q]);
        float4 e0 = __ldg(&W2[2 * q]);
        float4 e1 = __ldg(&W2[2 * q + 1]);
        float h0 = fmaxf(fmaf(s, w1.x, bb.x), 0.0f);
        float h1 = fmaxf(fmaf(s, w1.y, bb.y), 0.0f);
        float h2 = fmaxf(fmaf(s, w1.z, bb.z), 0.0f);
        float h3 = fmaxf(fmaf(s, w1.w, bb.w), 0.0f);
        g0 = fmaf(h0, e0.x, g0); g1 = fmaf(h0, e0.y, g1);
        g0 = fmaf(h1, e0.z, g0); g1 = fmaf(h1, e0.w, g1);
        g0 = fmaf(h2, e1.x, g0); g1 = fmaf(h2, e1.y, g1);
        g0 = fmaf(h3, e1.z, g0); g1 = fmaf(h3, e1.w, g1);
    }
}

// per-node layer-2 input: t = d * g(d*acc1), d = rsqrt(deg+1);
// acc2 initialized to t (self-loop term). 2 nodes/thread.
__global__ __launch_bounds__(256) void k_node2(const float4* __restrict__ W1,
                                               const float4* __restrict__ b1,
                                               const float4* __restrict__ W2) {
    int i = blockIdx.x * blockDim.x + threadIdx.x;
    if (i >= NN / 2) return;
    int2   dg = reinterpret_cast<const int2*>(g_deg)[i];
    float2 a  = reinterpret_cast<const float2*>(g_acc1)[i];
    float d0 = rsqrtf((float)(dg.x + 1));
    float d1 = rsqrtf((float)(dg.y + 1));
    float s0 = d0 * a.x;
    float s1 = d1 * a.y;
    float p0, p1, q0, q1;
    if (g_fullpath == 0) {
        float ap0 = g_Ap[0], ap1 = g_Ap[1];
        float am0 = g_Am[0], am1 = g_Am[1];
        p0 = s0 * (s0 > 0.0f ? ap0 : am0);  p1 = s0 * (s0 > 0.0f ? ap1 : am1);
        q0 = s1 * (s1 > 0.0f ? ap0 : am0);  q1 = s1 * (s1 > 0.0f ? ap1 : am1);
    } else {
        mlp_full(s0, W1, b1, W2, p0, p1);
        mlp_full(s1, W1, b1, W2, q0, q1);
    }
    float4 t = make_float4(d0 * p0, d0 * p1, d1 * q0, d1 * q1);
    reinterpret_cast<float4*>(g_t)[i]    = t;
    reinterpret_cast<float4*>(g_acc2)[i] = t;   // self-loop folded into init
}

// scatter layer-2 messages: acc2[col] += t[row]; 4 edges per thread
__global__ __launch_bounds__(256) void k_scat2(const int* __restrict__ row,
                                               const int* __restrict__ col, int E) {
    int i = (blockIdx.x * blockDim.x + threadIdx.x) * 4;
    if (i + 3 < E) {
        int4 r = __ldcs(reinterpret_cast<const int4*>(row + i));
        int4 c = __ldcs(reinterpret_cast<const int4*>(col + i));
        float2 t0 = __ldg(&g_t[r.x]);
        float2 t1 = __ldg(&g_t[r.y]);
        float2 t2 = __ldg(&g_t[r.z]);
        float2 t3 = __ldg(&g_t[r.w]);
        red_add_v2(&g_acc2[c.x], t0);
        red_add_v2(&g_acc2[c.y], t1);
        red_add_v2(&g_acc2[c.z], t2);
        red_add_v2(&g_acc2[c.w], t3);
    }
}

// final: out = d*acc2 + b2 (d = rsqrt(deg+1)), log_softmax over 2 classes;
// 2 nodes/thread. Re-zeroes g_deg after reading (graph replay invariant).
__global__ __launch_bounds__(256) void k_out(const float* __restrict__ b2,
                                             float4* __restrict__ out) {
    int i = blockIdx.x * blockDim.x + threadIdx.x;
    if (i >= NN / 2) return;
    float b20 = __ldg(&b2[0]);
    float b21 = __ldg(&b2[1]);
    int2   dg = reinterpret_cast<const int2*>(g_deg)[i];
    float4 a  = reinterpret_cast<const float4*>(g_acc2)[i];
    float d0 = rsqrtf((float)(dg.x + 1));
    float d1 = rsqrtf((float)(dg.y + 1));
    float o0 = fmaf(d0, a.x, b20);
    float o1 = fmaf(d0, a.y, b21);
    float o2 = fmaf(d1, a.z, b20);
    float o3 = fmaf(d1, a.w, b21);
    float m0  = fmaxf(o0, o1);
    float l0  = m0 + log1pf(__expf(fminf(o0, o1) - m0));
    float m1  = fmaxf(o2, o3);
    float l1  = m1 + log1pf(__expf(fminf(o2, o3) - m1));
    out[i] = make_float4(o0 - l0, o1 - l0, o2 - l1, o3 - l1);
    // restore deg=0 for the next replay (2 nodes per thread)
    reinterpret_cast<int2*>(g_deg)[i] = make_int2(0, 0);
}

// ---------------------------------------------------------------------------
extern "C" void kernel_launch(void* const* d_in, const int* in_sizes, int n_in,
                              void* d_out, int out_size) {
    const float* x   = (const float*)d_in[0];
    const int*   ei  = (const int*)d_in[1];
    const float* W1  = (const float*)d_in[2];
    const float* b1  = (const float*)d_in[3];
    const float* W2  = (const float*)d_in[4];
    const float* b2  = (const float*)d_in[5];

    const int E = in_sizes[1] / 2;      // edge_index is [2, E]
    const int* row = ei;                // source
    const int* col = ei + E;            // target

    const int TB = 256;
    const int n4Blocks = (NN / 4 + TB - 1) / TB;
    const int n2Blocks = (NN / 2 + TB - 1) / TB;
    const int edgeBlocks = (E / 4 + TB - 1) / TB;   // 4 edges per thread

    k_deg  <<<edgeBlocks, TB>>>(col, E);
    k_prep <<<n4Blocks + 1, TB>>>((const float4*)x, W1, b1, W2); // +1: weight fold
    k_scat1<<<edgeBlocks, TB>>>(row, col, E);
    k_node2<<<n2Blocks, TB>>>((const float4*)W1, (const float4*)b1,
                              (const float4*)W2);
    k_scat2<<<edgeBlocks, TB>>>(row, col, E);
    k_out  <<<n2Blocks, TB>>>(b2, (float4*)d_out);
}

// round 13
// speedup vs baseline: 1.0001x; 1.0001x over previous
#include <cuda_runtime.h>
#include <cstdint>

#define NN 1000000
#define NE 16000000

// ---- scratch (device globals; no allocations allowed) ----
// g_deg is zero at module load; every call re-zeroes it in k_out's tail,
// so each kernel_launch call sees deg==0 at entry (state invariant).
__device__ int    g_deg[NN];
__device__ float  g_u[NN];
__device__ float  g_acc1[NN];    // initialized to u[i] (self-loop term)
__device__ float2 g_t[NN];
__device__ float2 g_acc2[NN];    // initialized to t[i] (self-loop term)

// folded MLP coefficients (valid iff b1 == 0): g(s) = s>0 ? s*Ap : s*Am
__device__ float  g_Ap[2];
__device__ float  g_Am[2];
__device__ int    g_fullpath;   // nonzero if any b1[j] != 0 -> exact full MLP

// ---- no-return global reductions ----
__device__ __forceinline__ void red_add_u32(int* addr) {
    asm volatile("red.global.add.u32 [%0], 1;" :: "l"(addr) : "memory");
}
__device__ __forceinline__ void red_add_f32(float* addr, float v) {
    asm volatile("red.global.add.f32 [%0], %1;" :: "l"(addr), "f"(v) : "memory");
}
__device__ __forceinline__ void red_add_v2(float2* addr, float2 v) {
    asm volatile("red.global.add.v2.f32 [%0], {%1, %2};"
                 :: "l"(addr), "f"(v.x), "f"(v.y) : "memory");
}

// ---------------------------------------------------------------------------
// degree count over target (col) indices; 4 edges per thread (flat mapping)
__global__ __launch_bounds__(512) void k_deg(const int* __restrict__ col, int E) {
    int i = (blockIdx.x * blockDim.x + threadIdx.x) * 4;
    if (i + 3 < E) {
        int4 c = __ldcs(reinterpret_cast<const int4*>(col + i));
        red_add_u32(&g_deg[c.x]);
        red_add_u32(&g_deg[c.y]);
        red_add_u32(&g_deg[c.z]);
        red_add_u32(&g_deg[c.w]);
    }
}

// u = rsqrt(deg+1) * x; acc1 = u (self-loop term). 4 nodes/thread.
// Extra block (blockIdx.x == gridDim.x-1) folds MLP weights into A+/A-.
__global__ __launch_bounds__(256) void k_prep(const float4* __restrict__ x4,
                                              const float* __restrict__ W1,
                                              const float* __restrict__ b1,
                                              const float* __restrict__ W2) {
    if (blockIdx.x == gridDim.x - 1) {
        if (threadIdx.x < 32) {
            int j = threadIdx.x;
            float w   = (j < 16) ? W1[j] : 0.0f;
            float bb  = (j < 16) ? b1[j] : 0.0f;
            float w20 = (j < 16) ? W2[2 * j]     : 0.0f;
            float w21 = (j < 16) ? W2[2 * j + 1] : 0.0f;
            float ap0 = (w > 0.0f) ? w * w20 : 0.0f;
            float ap1 = (w > 0.0f) ? w * w21 : 0.0f;
            float am0 = (w < 0.0f) ? w * w20 : 0.0f;
            float am1 = (w < 0.0f) ? w * w21 : 0.0f;
            int   nz  = (bb != 0.0f) ? 1 : 0;
#pragma unroll
            for (int off = 16; off > 0; off >>= 1) {
                ap0 += __shfl_down_sync(0xffffffffu, ap0, off);
                ap1 += __shfl_down_sync(0xffffffffu, ap1, off);
                am0 += __shfl_down_sync(0xffffffffu, am0, off);
                am1 += __shfl_down_sync(0xffffffffu, am1, off);
                nz  += __shfl_down_sync(0xffffffffu, nz,  off);
            }
            if (j == 0) {
                g_Ap[0] = ap0; g_Ap[1] = ap1;
                g_Am[0] = am0; g_Am[1] = am1;
                g_fullpath = nz;
            }
        }
        return;
    }
    int i = blockIdx.x * blockDim.x + threadIdx.x;
    if (i >= NN / 4) return;
    int4   dg = reinterpret_cast<const int4*>(g_deg)[i];
    float4 xv = __ldg(&x4[i]);
    float4 u;
    u.x = rsqrtf((float)(dg.x + 1)) * xv.x;
    u.y = rsqrtf((float)(dg.y + 1)) * xv.y;
    u.z = rsqrtf((float)(dg.z + 1)) * xv.z;
    u.w = rsqrtf((float)(dg.w + 1)) * xv.w;
    reinterpret_cast<float4*>(g_u)[i]    = u;
    reinterpret_cast<float4*>(g_acc1)[i] = u;   // self-loop folded into init
}

// scatter layer-1 messages: acc1[col] += u[row]; 4 edges per thread
__global__ __launch_bounds__(512) void k_scat1(const int* __restrict__ row,
                                               const int* __restrict__ col, int E) {
    int i = (blockIdx.x * blockDim.x + threadIdx.x) * 4;
    if (i + 3 < E) {
        int4 r = __ldcs(reinterpret_cast<const int4*>(row + i));
        int4 c = __ldcs(reinterpret_cast<const int4*>(col + i));
        float u0 = __ldg(&g_u[r.x]);
        float u1 = __ldg(&g_u[r.y]);
        float u2 = __ldg(&g_u[r.z]);
        float u3 = __ldg(&g_u[r.w]);
        red_add_f32(&g_acc1[c.x], u0);
        red_add_f32(&g_acc1[c.y], u1);
        red_add_f32(&g_acc1[c.z], u2);
        red_add_f32(&g_acc1[c.w], u3);
    }
}

// full exact MLP (fallback path, used only if b1 != 0)
__device__ __noinline__ void mlp_full(float s, const float4* W1,
                                      const float4* b1, const float4* W2,
                                      float& g0, float& g1) {
    g0 = 0.0f; g1 = 0.0f;
#pragma unroll
    for (int q = 0; q < 4; q++) {
        float4 w1 = __ldg(&W1[q]);
        float4 bb = __ldg(&b1[q]);
        float4 e0 = __ldg(&W2[2 * q]);
        float4 e1 = __ldg(&W2[2 * q + 1]);
        float h0 = fmaxf(fmaf(s, w1.x, bb.x), 0.0f);
        float h1 = fmaxf(fmaf(s, w1.y, bb.y), 0.0f);
        float h2 = fmaxf(fmaf(s, w1.z, bb.z), 0.0f);
        float h3 = fmaxf(fmaf(s, w1.w, bb.w), 0.0f);
        g0 = fmaf(h0, e0.x, g0); g1 = fmaf(h0, e0.y, g1);
        g0 = fmaf(h1, e0.z, g0); g1 = fmaf(h1, e0.w, g1);
        g0 = fmaf(h2, e1.x, g0); g1 = fmaf(h2, e1.y, g1);
        g0 = fmaf(h3, e1.z, g0); g1 = fmaf(h3, e1.w, g1);
    }
}

// per-node layer-2 input: t = d * g(d*acc1), d = rsqrt(deg+1);
// acc2 initialized to t (self-loop term). 2 nodes/thread.
__global__ __launch_bounds__(256) void k_node2(const float4* __restrict__ W1,
                                               const float4* __restrict__ b1,
                                               const float4* __restrict__ W2) {
    int i = blockIdx.x * blockDim.x + threadIdx.x;
    if (i >= NN / 2) return;
    int2   dg = reinterpret_cast<const int2*>(g_deg)[i];
    float2 a  = reinterpret_cast<const float2*>(g_acc1)[i];
    float d0 = rsqrtf((float)(dg.x + 1));
    float d1 = rsqrtf((float)(dg.y + 1));
    float s0 = d0 * a.x;
    float s1 = d1 * a.y;
    float p0, p1, q0, q1;
    if (g_fullpath == 0) {
        float ap0 = g_Ap[0], ap1 = g_Ap[1];
        float am0 = g_Am[0], am1 = g_Am[1];
        p0 = s0 * (s0 > 0.0f ? ap0 : am0);  p1 = s0 * (s0 > 0.0f ? ap1 : am1);
        q0 = s1 * (s1 > 0.0f ? ap0 : am0);  q1 = s1 * (s1 > 0.0f ? ap1 : am1);
    } else {
        mlp_full(s0, W1, b1, W2, p0, p1);
        mlp_full(s1, W1, b1, W2, q0, q1);
    }
    float4 t = make_float4(d0 * p0, d0 * p1, d1 * q0, d1 * q1);
    reinterpret_cast<float4*>(g_t)[i]    = t;
    reinterpret_cast<float4*>(g_acc2)[i] = t;   // self-loop folded into init
}

// scatter layer-2 messages: acc2[col] += t[row]; 4 edges per thread
__global__ __launch_bounds__(512) void k_scat2(const int* __restrict__ row,
                                               const int* __restrict__ col, int E) {
    int i = (blockIdx.x * blockDim.x + threadIdx.x) * 4;
    if (i + 3 < E) {
        int4 r = __ldcs(reinterpret_cast<const int4*>(row + i));
        int4 c = __ldcs(reinterpret_cast<const int4*>(col + i));
        float2 t0 = __ldg(&g_t[r.x]);
        float2 t1 = __ldg(&g_t[r.y]);
        float2 t2 = __ldg(&g_t[r.z]);
        float2 t3 = __ldg(&g_t[r.w]);
        red_add_v2(&g_acc2[c.x], t0);
        red_add_v2(&g_acc2[c.y], t1);
        red_add_v2(&g_acc2[c.z], t2);
        red_add_v2(&g_acc2[c.w], t3);
    }
}

// final: out = d*acc2 + b2 (d = rsqrt(deg+1)), log_softmax over 2 classes;
// 2 nodes/thread. Re-zeroes g_deg after reading (graph replay invariant).
__global__ __launch_bounds__(256) void k_out(const float* __restrict__ b2,
                                             float4* __restrict__ out) {
    int i = blockIdx.x * blockDim.x + threadIdx.x;
    if (i >= NN / 2) return;
    float b20 = __ldg(&b2[0]);
    float b21 = __ldg(&b2[1]);
    int2   dg = reinterpret_cast<const int2*>(g_deg)[i];
    float4 a  = reinterpret_cast<const float4*>(g_acc2)[i];
    float d0 = rsqrtf((float)(dg.x + 1));
    float d1 = rsqrtf((float)(dg.y + 1));
    float o0 = fmaf(d0, a.x, b20);
    float o1 = fmaf(d0, a.y, b21);
    float o2 = fmaf(d1, a.z, b20);
    float o3 = fmaf(d1, a.w, b21);
    float m0  = fmaxf(o0, o1);
    float l0  = m0 + log1pf(__expf(fminf(o0, o1) - m0));
    float m1  = fmaxf(o2, o3);
    float l1  = m1 + log1pf(__expf(fminf(o2, o3) - m1));
    out[i] = make_float4(o0 - l0, o1 - l0, o2 - l1, o3 - l1);
    // restore deg=0 for the next replay (2 nodes per thread)
    reinterpret_cast<int2*>(g_deg)[i] = make_int2(0, 0);
}

// ---------------------------------------------------------------------------
extern "C" void kernel_launch(void* const* d_in, const int* in_sizes, int n_in,
                              void* d_out, int out_size) {
    const float* x   = (const float*)d_in[0];
    const int*   ei  = (const int*)d_in[1];
    const float* W1  = (const float*)d_in[2];
    const float* b1  = (const float*)d_in[3];
    const float* W2  = (const float*)d_in[4];
    const float* b2  = (const float*)d_in[5];

    const int E = in_sizes[1] / 2;      // edge_index is [2, E]
    const int* row = ei;                // source
    const int* col = ei + E;            // target

    const int TBE = 512;                // edge kernels
    const int TBN = 256;                // node kernels
    const int n4Blocks = (NN / 4 + TBN - 1) / TBN;
    const int n2Blocks = (NN / 2 + TBN - 1) / TBN;
    const int edgeBlocks = (E / 4 + TBE - 1) / TBE;   // 4 edges per thread

    k_deg  <<<edgeBlocks, TBE>>>(col, E);
    k_prep <<<n4Blocks + 1, TBN>>>((const float4*)x, W1, b1, W2); // +1: weight fold
    k_scat1<<<edgeBlocks, TBE>>>(row, col, E);
    k_node2<<<n2Blocks, TBN>>>((const float4*)W1, (const float4*)b1,
                               (const float4*)W2);
    k_scat2<<<edgeBlocks, TBE>>>(row, col, E);
    k_out  <<<n2Blocks, TBN>>>(b2, (float4*)d_out);
}

// round 14
// speedup vs baseline: 1.0002x; 1.0001x over previous
#include <cuda_runtime.h>
#include <cstdint>

#define NN 1000000
#define NE 16000000

// ---- scratch (device globals; no allocations allowed) ----
// g_deg is zero at module load; every call re-zeroes it in k_out's tail,
// so each kernel_launch call sees deg==0 at entry (state invariant).
__device__ int    g_deg[NN];
__device__ float  g_u[NN];
__device__ float  g_acc1[NN];    // initialized to u[i] (self-loop term)
__device__ float2 g_t[NN];
__device__ float2 g_acc2[NN];    // initialized to t[i] (self-loop term)

// folded MLP coefficients (valid iff b1 == 0): g(s) = s>0 ? s*Ap : s*Am
__device__ float  g_Ap[2];
__device__ float  g_Am[2];
__device__ int    g_fullpath;   // nonzero if any b1[j] != 0 -> exact full MLP

// ---- no-return global reductions ----
__device__ __forceinline__ void red_add_u32(int* addr) {
    asm volatile("red.global.add.u32 [%0], 1;" :: "l"(addr) : "memory");
}
__device__ __forceinline__ void red_add_f32(float* addr, float v) {
    asm volatile("red.global.add.f32 [%0], %1;" :: "l"(addr), "f"(v) : "memory");
}
__device__ __forceinline__ void red_add_v2(float2* addr, float2 v) {
    asm volatile("red.global.add.v2.f32 [%0], {%1, %2};"
                 :: "l"(addr), "f"(v.x), "f"(v.y) : "memory");
}

// ---------------------------------------------------------------------------
// degree count over target (col) indices; 4 edges per thread (flat mapping)
__global__ __launch_bounds__(256) void k_deg(const int* __restrict__ col, int E) {
    int i = (blockIdx.x * blockDim.x + threadIdx.x) * 4;
    if (i + 3 < E) {
        int4 c = __ldcs(reinterpret_cast<const int4*>(col + i));
        red_add_u32(&g_deg[c.x]);
        red_add_u32(&g_deg[c.y]);
        red_add_u32(&g_deg[c.z]);
        red_add_u32(&g_deg[c.w]);
    }
}

// u = rsqrt(deg+1) * x; acc1 = u (self-loop term). 4 nodes/thread.
// Extra block (blockIdx.x == gridDim.x-1) folds MLP weights into A+/A-.
__global__ __launch_bounds__(256) void k_prep(const float4* __restrict__ x4,
                                              const float* __restrict__ W1,
                                              const float* __restrict__ b1,
                                              const float* __restrict__ W2) {
    if (blockIdx.x == gridDim.x - 1) {
        if (threadIdx.x < 32) {
            int j = threadIdx.x;
            float w   = (j < 16) ? W1[j] : 0.0f;
            float bb  = (j < 16) ? b1[j] : 0.0f;
            float w20 = (j < 16) ? W2[2 * j]     : 0.0f;
            float w21 = (j < 16) ? W2[2 * j + 1] : 0.0f;
            float ap0 = (w > 0.0f) ? w * w20 : 0.0f;
            float ap1 = (w > 0.0f) ? w * w21 : 0.0f;
            float am0 = (w < 0.0f) ? w * w20 : 0.0f;
            float am1 = (w < 0.0f) ? w * w21 : 0.0f;
            int   nz  = (bb != 0.0f) ? 1 : 0;
#pragma unroll
            for (int off = 16; off > 0; off >>= 1) {
                ap0 += __shfl_down_sync(0xffffffffu, ap0, off);
                ap1 += __shfl_down_sync(0xffffffffu, ap1, off);
                am0 += __shfl_down_sync(0xffffffffu, am0, off);
                am1 += __shfl_down_sync(0xffffffffu, am1, off);
                nz  += __shfl_down_sync(0xffffffffu, nz,  off);
            }
            if (j == 0) {
                g_Ap[0] = ap0; g_Ap[1] = ap1;
                g_Am[0] = am0; g_Am[1] = am1;
                g_fullpath = nz;
            }
        }
        return;
    }
    int i = blockIdx.x * blockDim.x + threadIdx.x;
    if (i >= NN / 4) return;
    int4   dg = reinterpret_cast<const int4*>(g_deg)[i];
    float4 xv = __ldg(&x4[i]);
    float4 u;
    u.x = rsqrtf((float)(dg.x + 1)) * xv.x;
    u.y = rsqrtf((float)(dg.y + 1)) * xv.y;
    u.z = rsqrtf((float)(dg.z + 1)) * xv.z;
    u.w = rsqrtf((float)(dg.w + 1)) * xv.w;
    reinterpret_cast<float4*>(g_u)[i]    = u;
    reinterpret_cast<float4*>(g_acc1)[i] = u;   // self-loop folded into init
}

// scatter layer-1 messages: acc1[col] += u[row]; 4 edges per thread
__global__ __launch_bounds__(256) void k_scat1(const int* __restrict__ row,
                                               const int* __restrict__ col, int E) {
    int i = (blockIdx.x * blockDim.x + threadIdx.x) * 4;
    if (i + 3 < E) {
        int4 r = __ldcs(reinterpret_cast<const int4*>(row + i));
        int4 c = __ldcs(reinterpret_cast<const int4*>(col + i));
        float u0 = __ldg(&g_u[r.x]);
        float u1 = __ldg(&g_u[r.y]);
        float u2 = __ldg(&g_u[r.z]);
        float u3 = __ldg(&g_u[r.w]);
        red_add_f32(&g_acc1[c.x], u0);
        red_add_f32(&g_acc1[c.y], u1);
        red_add_f32(&g_acc1[c.z], u2);
        red_add_f32(&g_acc1[c.w], u3);
    }
}

// full exact MLP (fallback path, used only if b1 != 0)
__device__ __noinline__ void mlp_full(float s, const float4* W1,
                                      const float4* b1, const float4* W2,
                                      float& g0, float& g1) {
    g0 = 0.0f; g1 = 0.0f;
#pragma unroll
    for (int q = 0; q < 4; q++) {
        float4 w1 = __ldg(&W1[q]);
        float4 bb = __ldg(&b1[q]);
        float4 e0 = __ldg(&W2[2 * q]);
        float4 e1 = __ldg(&W2[2 * q + 1]);
        float h0 = fmaxf(fmaf(s, w1.x, bb.x), 0.0f);
        float h1 = fmaxf(fmaf(s, w1.y, bb.y), 0.0f);
        float h2 = fmaxf(fmaf(s, w1.z, bb.z), 0.0f);
        float h3 = fmaxf(fmaf(s, w1.w, bb.w), 0.0f);
        g0 = fmaf(h0, e0.x, g0); g1 = fmaf(h0, e0.y, g1);
        g0 = fmaf(h1, e0.z, g0); g1 = fmaf(h1, e0.w, g1);
        g0 = fmaf(h2, e1.x, g0); g1 = fmaf(h2, e1.y, g1);
        g0 = fmaf(h3, e1.z, g0); g1 = fmaf(h3, e1.w, g1);
    }
}

// per-node layer-2 input: t = d * g(d*acc1), d = rsqrt(deg+1);
// acc2 initialized to t (self-loop term). 2 nodes/thread.
__global__ __launch_bounds__(256) void k_node2(const float4* __restrict__ W1,
                                               const float4* __restrict__ b1,
                                               const float4* __restrict__ W2) {
    int i = blockIdx.x * blockDim.x + threadIdx.x;
    if (i >= NN / 2) return;
    int2   dg = reinterpret_cast<const int2*>(g_deg)[i];
    float2 a  = reinterpret_cast<const float2*>(g_acc1)[i];
    float d0 = rsqrtf((float)(dg.x + 1));
    float d1 = rsqrtf((float)(dg.y + 1));
    float s0 = d0 * a.x;
    float s1 = d1 * a.y;
    float p0, p1, q0, q1;
    if (g_fullpath == 0) {
        float ap0 = g_Ap[0], ap1 = g_Ap[1];
        float am0 = g_Am[0], am1 = g_Am[1];
        p0 = s0 * (s0 > 0.0f ? ap0 : am0);  p1 = s0 * (s0 > 0.0f ? ap1 : am1);
        q0 = s1 * (s1 > 0.0f ? ap0 : am0);  q1 = s1 * (s1 > 0.0f ? ap1 : am1);
    } else {
        mlp_full(s0, W1, b1, W2, p0, p1);
        mlp_full(s1, W1, b1, W2, q0, q1);
    }
    float4 t = make_float4(d0 * p0, d0 * p1, d1 * q0, d1 * q1);
    reinterpret_cast<float4*>(g_t)[i]    = t;
    reinterpret_cast<float4*>(g_acc2)[i] = t;   // self-loop folded into init
}

// scatter layer-2 messages: acc2[col] += t[row]; 4 edges per thread
__global__ __launch_bounds__(256) void k_scat2(const int* __restrict__ row,
                                               const int* __restrict__ col, int E) {
    int i = (blockIdx.x * blockDim.x + threadIdx.x) * 4;
    if (i + 3 < E) {
        int4 r = __ldcs(reinterpret_cast<const int4*>(row + i));
        int4 c = __ldcs(reinterpret_cast<const int4*>(col + i));
        float2 t0 = __ldg(&g_t[r.x]);
        float2 t1 = __ldg(&g_t[r.y]);
        float2 t2 = __ldg(&g_t[r.z]);
        float2 t3 = __ldg(&g_t[r.w]);
        red_add_v2(&g_acc2[c.x], t0);
        red_add_v2(&g_acc2[c.y], t1);
        red_add_v2(&g_acc2[c.z], t2);
        red_add_v2(&g_acc2[c.w], t3);
    }
}

// final: out = d*acc2 + b2 (d = rsqrt(deg+1)), log_softmax over 2 classes;
// 2 nodes/thread. Re-zeroes g_deg after reading (graph replay invariant).
__global__ __launch_bounds__(256) void k_out(const float* __restrict__ b2,
                                             float4* __restrict__ out) {
    int i = blockIdx.x * blockDim.x + threadIdx.x;
    if (i >= NN / 2) return;
    float b20 = __ldg(&b2[0]);
    float b21 = __ldg(&b2[1]);
    int2   dg = reinterpret_cast<const int2*>(g_deg)[i];
    float4 a  = reinterpret_cast<const float4*>(g_acc2)[i];
    float d0 = rsqrtf((float)(dg.x + 1));
    float d1 = rsqrtf((float)(dg.y + 1));
    float o0 = fmaf(d0, a.x, b20);
    float o1 = fmaf(d0, a.y, b21);
    float o2 = fmaf(d1, a.z, b20);
    float o3 = fmaf(d1, a.w, b21);
    float m0  = fmaxf(o0, o1);
    float l0  = m0 + log1pf(__expf(fminf(o0, o1) - m0));
    float m1  = fmaxf(o2, o3);
    float l1  = m1 + log1pf(__expf(fminf(o2, o3) - m1));
    out[i] = make_float4(o0 - l0, o1 - l0, o2 - l1, o3 - l1);
    // restore deg=0 for the next replay (2 nodes per thread)
    reinterpret_cast<int2*>(g_deg)[i] = make_int2(0, 0);
}

// ---------------------------------------------------------------------------
extern "C" void kernel_launch(void* const* d_in, const int* in_sizes, int n_in,
                              void* d_out, int out_size) {
    const float* x   = (const float*)d_in[0];
    const int*   ei  = (const int*)d_in[1];
    const float* W1  = (const float*)d_in[2];
    const float* b1  = (const float*)d_in[3];
    const float* W2  = (const float*)d_in[4];
    const float* b2  = (const float*)d_in[5];

    const int E = in_sizes[1] / 2;      // edge_index is [2, E]
    const int* row = ei;                // source
    const int* col = ei + E;            // target

    const int TB = 256;
    const int n4Blocks = (NN / 4 + TB - 1) / TB;
    const int n2Blocks = (NN / 2 + TB - 1) / TB;
    const int edgeBlocks = (E / 4 + TB - 1) / TB;   // 4 edges per thread

    k_deg  <<<edgeBlocks, TB>>>(col, E);
    k_prep <<<n4Blocks + 1, TB>>>((const float4*)x, W1, b1, W2); // +1: weight fold
    k_scat1<<<edgeBlocks, TB>>>(row, col, E);
    k_node2<<<n2Blocks, TB>>>((const float4*)W1, (const float4*)b1,
                              (const float4*)W2);
    k_scat2<<<edgeBlocks, TB>>>(row, col, E);
    k_out  <<<n2Blocks, TB>>>(b2, (float4*)d_out);
}